// round 16
// baseline (speedup 1.0000x reference)
#include <cuda_runtime.h>
#include <cuda_fp16.h>
#include <cstdint>

#define SEQ 2048
#define DM 768
#define NH 12
#define HD 64
#define ROWS 8192
#define ZBN 48
#define NQKV 2304
typedef __half f16;

// ---------------- scratch ----------------
__device__ __align__(16) f16  g_x16[ROWS*DM];
__device__ __align__(16) f16  g_w16[4][DM*DM];     // Wq,Wk,Wv contiguous -> [2304x768]; Wo at [3]
__device__ __align__(16) float g_biasqkv[NQKV];
__device__ __align__(16) f16  g_qkv16[(long)ROWS*NQKV];
__device__ __align__(16) f16  g_q16[ROWS*DM], g_k16[ROWS*DM];
__device__ __align__(16) f16  g_vt[(long)ZBN*HD*SEQ];
__device__ __align__(16) float g_rsum[ZBN*SEQ];
__device__ __align__(16) f16  g_o16[ROWS*DM];

#define SWZ(o) ((o)^(((o)>>3)&0x70))
#define CPCOMMIT() asm volatile("cp.async.commit_group;":::"memory")
#define CPWAIT1()  asm volatile("cp.async.wait_group 1;":::"memory")
#define CPWAIT0()  asm volatile("cp.async.wait_group 0;":::"memory")
#define LOG2E 1.44269504f

__device__ __forceinline__ uint32_t smem_u32(const void* p){
    uint32_t a; asm("{ .reg .u64 t; cvta.to.shared.u64 t, %1; cvt.u32.u64 %0, t; }":"=r"(a):"l"(p)); return a;
}
__device__ __forceinline__ float ex2(float x){
    float y; asm("ex2.approx.f32 %0, %1;":"=f"(y):"f"(x)); return y;
}
__device__ __forceinline__ void ldm4(uint32_t* r, uint32_t base, int row0, int ks, int lane){
    uint32_t addr = base + SWZ((unsigned)((row0+(lane&15))<<7) + (unsigned)(((ks<<1)+(lane>>4))<<4));
    asm volatile("ldmatrix.sync.aligned.m8n8.x4.shared.b16 {%0,%1,%2,%3}, [%4];"
        :"=r"(r[0]),"=r"(r[1]),"=r"(r[2]),"=r"(r[3]):"r"(addr));
}
__device__ __forceinline__ void ldm4p(uint32_t* r, uint32_t addr){
    asm volatile("ldmatrix.sync.aligned.m8n8.x4.shared.b16 {%0,%1,%2,%3}, [%4];"
        :"=r"(r[0]),"=r"(r[1]),"=r"(r[2]),"=r"(r[3]):"r"(addr));
}
__device__ __forceinline__ uint32_t ldmaddr(int row0, int ks, int lane){
    return SWZ((unsigned)((row0+(lane&15))<<7) + (unsigned)(((ks<<1)+(lane>>4))<<4));
}
__device__ __forceinline__ void mma_hf(float* d, const uint32_t* a, uint32_t b0, uint32_t b1){
    asm volatile("mma.sync.aligned.m16n8k16.row.col.f32.f16.f16.f32 "
        "{%0,%1,%2,%3},{%4,%5,%6,%7},{%8,%9},{%0,%1,%2,%3};"
        : "+f"(d[0]),"+f"(d[1]),"+f"(d[2]),"+f"(d[3])
        : "r"(a[0]),"r"(a[1]),"r"(a[2]),"r"(a[3]),"r"(b0),"r"(b1));
}
// pack two fp32 scores -> fp16x2, then one f16x2 MUFU exp2. Result = packed P.
__device__ __forceinline__ unsigned packexp2(float a, float b){
    unsigned s,r;
    asm("cvt.rn.f16x2.f32 %0, %1, %2;":"=r"(s):"f"(b),"f"(a));   // hi=b, lo=a
    asm("ex2.approx.f16x2 %0, %1;":"=r"(r):"r"(s));
    return r;
}
template<int ROWSN, typename T>
__device__ __forceinline__ void cpfill(uint32_t s, const T* __restrict__ g, int ldK, int tid){
#pragma unroll
    for(int i=0;i<ROWSN/32;i++){
        int idx=tid+(i<<8); int r=idx>>3, c=idx&7;
        uint32_t dst=s+SWZ((unsigned)((r<<7)+(c<<4)));
        const void* src=g+(long)r*ldK+(c<<3);
        asm volatile("cp.async.cg.shared.global [%0], [%1], 16;"::"r"(dst),"l"(src):"memory");
    }
}

// ---------------------------------------------------------------------------
// prep: all fp32->fp16 conversions + bias concat in one launch.
// ---------------------------------------------------------------------------
__global__ __launch_bounds__(256) void prep(
    const float* __restrict__ x,
    const float* __restrict__ Wq,const float* __restrict__ Wk,
    const float* __restrict__ Wv,const float* __restrict__ Wo,
    const float* __restrict__ bk,const float* __restrict__ bv,
    f16* __restrict__ x16, f16* __restrict__ w16, float* __restrict__ biasqkv)
{
    const long NX=(long)ROWS*DM, NW=(long)DM*DM;
    int y=blockIdx.y;
    long i=((long)blockIdx.x*256+threadIdx.x)*4;
    const float* src; f16* dst; long n;
    if(y==4){ src=x; dst=x16; n=NX; }
    else { src=(y==0)?Wq:(y==1)?Wk:(y==2)?Wv:Wo; dst=w16+(long)y*NW; n=NW; }
    if(i<n){
        float4 v=*reinterpret_cast<const float4*>(src+i);
        __half2 a=__floats2half2_rn(v.x,v.y), b=__floats2half2_rn(v.z,v.w);
        *reinterpret_cast<uint2*>(dst+i)=make_uint2(*reinterpret_cast<unsigned*>(&a),*reinterpret_cast<unsigned*>(&b));
    }
    if(y==0){
        int j=blockIdx.x*256+threadIdx.x;
        if(j<NQKV) biasqkv[j]=(j<DM)?0.f:((j<2*DM)?bk[j-DM]:bv[j-2*DM]);
    }
}

// ---------------------------------------------------------------------------
// fp16 GEMM. MODE 0: fp32 out +bias +resid. MODE 1: fp16 out +bias.
// ---------------------------------------------------------------------------
template<int MODE>
__global__ __launch_bounds__(256) void gemm_h(
    const f16* __restrict__ a16,const f16* __restrict__ b16,
    const float* __restrict__ bias,const float* __restrict__ resid,
    float* __restrict__ Cf, f16* __restrict__ Ch, int K,int N)
{
    extern __shared__ char smem[];
    const uint32_t sb=smem_u32(smem);
    const int tid=threadIdx.x, wid=tid>>5, lane=tid&31;
    const int m0=blockIdx.y<<7, n0=blockIdx.x<<7;
    const int wm=(wid&3)<<5, wn=(wid>>2)<<6;
    const f16* A=a16+(long)m0*K;
    const f16* B=b16+(long)n0*K;
    const int NS=K>>6;

    cpfill<128>(sb,       A, K, tid);
    cpfill<128>(sb+16384, B, K, tid);
    CPCOMMIT();

    float acc[2][8][4]={};
    for(int s=0;s<NS;s++){
        if(s+1<NS){
            uint32_t st=sb+((s+1)&1)*32768;
            cpfill<128>(st,       A+(s+1)*64, K, tid);
            cpfill<128>(st+16384, B+(s+1)*64, K, tid);
            CPCOMMIT(); CPWAIT1();
        } else CPWAIT0();
        __syncthreads();
        const uint32_t sA=sb+(s&1)*32768, sB=sA+16384;
#pragma unroll
        for(int ks=0;ks<4;ks++){
            uint32_t av[2][4];
            ldm4(av[0], sA, wm,    ks, lane); ldm4(av[1], sA, wm+16, ks, lane);
            uint32_t bv[4][4];
#pragma unroll
            for(int j=0;j<4;j++) ldm4(bv[j], sB, wn+(j<<4), ks, lane);
#pragma unroll
            for(int mi=0;mi<2;mi++)
#pragma unroll
                for(int j=0;j<4;j++){
                    mma_hf(acc[mi][2*j],   av[mi], bv[j][0], bv[j][2]);
                    mma_hf(acc[mi][2*j+1], av[mi], bv[j][1], bv[j][3]);
                }
        }
        __syncthreads();
    }
#pragma unroll
    for(int mi=0;mi<2;mi++)
#pragma unroll
        for(int jj=0;jj<8;jj++){
            float* d=acc[mi][jj];
            int col=n0+wn+(jj<<3)+((lane&3)<<1);
            long row=m0+wm+(mi<<4)+(lane>>2);
            float2 v0=make_float2(d[0],d[1]), v1=make_float2(d[2],d[3]);
            float2 bv=*reinterpret_cast<const float2*>(bias+col);
            v0.x+=bv.x; v0.y+=bv.y; v1.x+=bv.x; v1.y+=bv.y;
            if(MODE==0){
                float2 r0=*reinterpret_cast<const float2*>(resid+row*N+col);
                float2 r1=*reinterpret_cast<const float2*>(resid+(row+8)*N+col);
                v0.x+=r0.x; v0.y+=r0.y; v1.x+=r1.x; v1.y+=r1.y;
                *reinterpret_cast<float2*>(Cf+row*N+col)=v0;
                *reinterpret_cast<float2*>(Cf+(row+8)*N+col)=v1;
            } else {
                __half2 p0=__floats2half2_rn(v0.x,v0.y), p1=__floats2half2_rn(v1.x,v1.y);
                *reinterpret_cast<unsigned*>(Ch+row*N+col)=*reinterpret_cast<unsigned*>(&p0);
                *reinterpret_cast<unsigned*>(Ch+(row+8)*N+col)=*reinterpret_cast<unsigned*>(&p1);
            }
        }
}

// ---- LN (no bias) on fp16 qkv; y=0 -> q (0.125*log2e folded), y=1 -> k (1.0) ----
__global__ __launch_bounds__(256) void ln2f16(
    const f16* __restrict__ qkv, const float* __restrict__ gq, const float* __restrict__ gk,
    f16* __restrict__ q16, f16* __restrict__ k16)
{
    const int y=blockIdx.y;
    const long row=blockIdx.x;
    const f16* p=qkv+row*NQKV+(y?DM:0);
    const float* gamma=y?gk:gq;
    const float scale=y?1.0f:(0.125f*LOG2E);   // log2e folded into q ONLY
    f16* out=(y?k16:q16)+row*DM;
    const int t=threadIdx.x;

    float v0=__half2float(p[t]),v1=__half2float(p[t+256]),v2=__half2float(p[t+512]);
    float s=v0+v1+v2, sq=v0*v0+v1*v1+v2*v2;
#pragma unroll
    for(int o=16;o;o>>=1){ s+=__shfl_xor_sync(~0u,s,o); sq+=__shfl_xor_sync(~0u,sq,o); }
    __shared__ float ss[8],sqs[8];
    int w=t>>5,ln=t&31;
    if(ln==0){ss[w]=s;sqs[w]=sq;} __syncthreads();
    if(w==0){ s=(ln<8)?ss[ln]:0.f; sq=(ln<8)?sqs[ln]:0.f;
#pragma unroll
        for(int o=4;o;o>>=1){ s+=__shfl_xor_sync(~0u,s,o); sq+=__shfl_xor_sync(~0u,sq,o); }
        if(ln==0){ss[0]=s;sqs[0]=sq;} }
    __syncthreads();
    float mu=ss[0]*(1.f/DM), var=sqs[0]*(1.f/DM)-mu*mu, rstd=rsqrtf(var+1e-5f)*scale;
#pragma unroll
    for(int g=0;g<3;g++){
        int c=t+g*256; float yv=((g==0?v0:g==1?v1:v2)-mu)*rstd*gamma[c];
        out[c]=__float2half_rn(yv);
    }
}

// ---------------------------------------------------------------------------
// Pass 1: rsum[z][k] = 1/sum_q 2^S (log2e pre-folded into q). K-tile resident.
// (unchanged from R15 — measured 95.6us with hoisting + fp32 ex2)
// ---------------------------------------------------------------------------
__global__ __launch_bounds__(256) void colsum_h(
    const f16* __restrict__ q16,const f16* __restrict__ k16, float* __restrict__ rsum)
{
    extern __shared__ char smem[];
    const uint32_t sb=smem_u32(smem);
    const int tid=threadIdx.x, wid=tid>>5, lane=tid&31;
    const int z=blockIdx.y, b=z/NH, h=z-b*NH;
    const int k0=blockIdx.x<<7;
    const int wm=(wid&3)<<5, wng=wid>>2;
    const f16* Kp=k16+(long)(b*SEQ+k0)*DM+h*HD;
    const f16* Qp=q16+(long)(b*SEQ)*DM+h*HD;

    cpfill<128>(sb, Kp, DM, tid);
    cpfill<128>(sb+16384, Qp, DM, tid);
    CPCOMMIT(); CPWAIT0();
    __syncthreads();

    uint32_t ka[2][4][4];
#pragma unroll
    for(int mi=0;mi<2;mi++)
#pragma unroll
        for(int ks=0;ks<4;ks++) ldm4(ka[mi][ks], sb, wm+(mi<<4), ks, lane);

    uint32_t qrel[4][4];
#pragma unroll
    for(int ks=0;ks<4;ks++)
#pragma unroll
        for(int j=0;j<4;j++) qrel[ks][j]=ldmaddr((wng<<6)+(j<<4), ks, lane)+sb+16384;

    float rs[2][2]={};
    for(int s=0;s<16;s++){
        if(s+1<16){
            cpfill<128>(sb+16384+((s+1)&1)*16384, Qp+(long)(s+1)*128*DM, DM, tid);
            CPCOMMIT(); CPWAIT1();
        } else CPWAIT0();
        __syncthreads();
        const uint32_t soff=(s&1)*16384;
        float acc[2][8][4]={};
#pragma unroll
        for(int ks=0;ks<4;ks++){
            uint32_t bv[4][4];
#pragma unroll
            for(int j=0;j<4;j++) ldm4p(bv[j], qrel[ks][j]+soff);
#pragma unroll
            for(int mi=0;mi<2;mi++)
#pragma unroll
                for(int j=0;j<4;j++){
                    mma_hf(acc[mi][2*j],   ka[mi][ks], bv[j][0], bv[j][2]);
                    mma_hf(acc[mi][2*j+1], ka[mi][ks], bv[j][1], bv[j][3]);
                }
        }
#pragma unroll
        for(int mi=0;mi<2;mi++)
#pragma unroll
            for(int jj=0;jj<8;jj++){
                float* d=acc[mi][jj];
                rs[mi][0]+=ex2(d[0])+ex2(d[1]);
                rs[mi][1]+=ex2(d[2])+ex2(d[3]);
            }
        __syncthreads();
    }
    __shared__ float cs[2][128];
#pragma unroll
    for(int mi=0;mi<2;mi++)
#pragma unroll
        for(int p=0;p<2;p++){
            float v=rs[mi][p];
            v+=__shfl_xor_sync(~0u,v,1); v+=__shfl_xor_sync(~0u,v,2);
            if((lane&3)==0) cs[wng][wm+(mi<<4)+(p<<3)+(lane>>2)]=v;
        }
    __syncthreads();
    if(tid<128){
        float s=cs[0][tid]+cs[1][tid];
        rsum[(long)z*SEQ+k0+tid]=1.f/s;
    }
}

// ---- qkv16 v-part -> vt fp16 [z][64][2048], scaled by rsum ----
__global__ void vtscale(const f16* __restrict__ qkv, const float* __restrict__ rsum,
                        f16* __restrict__ vt){
    __shared__ float tile[32][33];
    int b=blockIdx.z, c0=blockIdx.y*32, t0=blockIdx.x*32;
    int tx=threadIdx.x, ty=threadIdx.y;
#pragma unroll
    for(int j=0;j<32;j+=8)
        tile[ty+j][tx]=__half2float(qkv[(long)(b*SEQ+t0+ty+j)*NQKV+2*DM+c0+tx]);
    __syncthreads();
    int z=b*NH+(c0>>6), ch=c0&63;
    float rs=rsum[z*SEQ+t0+tx];
#pragma unroll
    for(int j=0;j<32;j+=8){
        long o=((long)z*HD+ch+ty+j)*SEQ+t0+tx;
        vt[o]=__float2half_rn(tile[tx][ty+j]*rs);
    }
}

// ---------------------------------------------------------------------------
// Pass 2: fused scores+PV (flash-style). Inline ldmatrix addressing (R13 style,
// low register pressure); P via cvt+ex2.f16x2 (one MUFU per 2 values).
// ---------------------------------------------------------------------------
__global__ __launch_bounds__(256) void flashpv_h(
    const f16* __restrict__ q16,const f16* __restrict__ k16,
    const f16* __restrict__ vt, f16* __restrict__ o16)
{
    extern __shared__ char smem[];
    const uint32_t sb=smem_u32(smem);
    const int tid=threadIdx.x, wid=tid>>5, lane=tid&31;
    const int z=blockIdx.y, b=z/NH, h=z-b*NH;
    const int q0=blockIdx.x<<7;
    const int wq=wid<<4;
    const f16* Qp=q16+(long)(b*SEQ+q0)*DM+h*HD;
    const f16* Kp=k16+(long)(b*SEQ)*DM+h*HD;
    const f16* Vp=vt+(long)z*HD*SEQ;

    cpfill<128>(sb, Qp, DM, tid);
    {
        uint32_t st=sb+16384;
        cpfill<64>(st,      Kp, DM, tid);
        cpfill<64>(st+8192, Vp, SEQ, tid);
    }
    CPCOMMIT(); CPWAIT0();
    __syncthreads();

    uint32_t qa[4][4];
#pragma unroll
    for(int ks=0;ks<4;ks++) ldm4(qa[ks], sb, wq, ks, lane);

    float accp[8][4]={};
    for(int s=0;s<32;s++){
        if(s+1<32){
            uint32_t st=sb+16384+((s+1)&1)*16384;
            cpfill<64>(st,      Kp+(long)(s+1)*64*DM, DM, tid);
            cpfill<64>(st+8192, Vp+(s+1)*64, SEQ, tid);
            CPCOMMIT(); CPWAIT1();
        } else CPWAIT0();
        __syncthreads();
        const uint32_t sK=sb+16384+(s&1)*16384, sV=sK+8192;

        float accs[8][4]={};
#pragma unroll
        for(int ks=0;ks<4;ks++){
            uint32_t bv[4][4];
#pragma unroll
            for(int j=0;j<4;j++) ldm4(bv[j], sK, j<<4, ks, lane);
#pragma unroll
            for(int j=0;j<4;j++){
                mma_hf(accs[2*j],   qa[ks], bv[j][0], bv[j][2]);
                mma_hf(accs[2*j+1], qa[ks], bv[j][1], bv[j][3]);
            }
        }
        uint32_t pa[4][4];
#pragma unroll
        for(int g=0;g<4;g++){
            float* cl=accs[2*g]; float* ch=accs[2*g+1];
            pa[g][0]=packexp2(cl[0],cl[1]);
            pa[g][1]=packexp2(cl[2],cl[3]);
            pa[g][2]=packexp2(ch[0],ch[1]);
            pa[g][3]=packexp2(ch[2],ch[3]);
        }
#pragma unroll
        for(int g=0;g<4;g++){
            uint32_t bv[4][4];
#pragma unroll
            for(int j=0;j<4;j++) ldm4(bv[j], sV, j<<4, g, lane);
#pragma unroll
            for(int j=0;j<4;j++){
                mma_hf(accp[2*j],   pa[g], bv[j][0], bv[j][2]);
                mma_hf(accp[2*j+1], pa[g], bv[j][1], bv[j][3]);
            }
        }
        __syncthreads();
    }
#pragma unroll
    for(int jj=0;jj<8;jj++){
        float* d=accp[jj];
        int col=h*HD+(jj<<3)+((lane&3)<<1);
        long row=(long)b*SEQ+q0+wq+(lane>>2);
        __half2 p0=__floats2half2_rn(d[0],d[1]), p1=__floats2half2_rn(d[2],d[3]);
        *reinterpret_cast<unsigned*>(o16+row*DM+col)=*reinterpret_cast<unsigned*>(&p0);
        *reinterpret_cast<unsigned*>(o16+(row+8)*DM+col)=*reinterpret_cast<unsigned*>(&p1);
    }
}

extern "C" void kernel_launch(void* const* d_in, const int* in_sizes, int n_in,
                              void* d_out, int out_size)
{
    const float* x =(const float*)d_in[0];
    const float* Wq=(const float*)d_in[1];
    const float* Wk=(const float*)d_in[2];
    const float* bk=(const float*)d_in[3];
    const float* Wv=(const float*)d_in[4];
    const float* bv=(const float*)d_in[5];
    const float* gq=(const float*)d_in[6];
    const float* gk=(const float*)d_in[7];
    const float* Wo=(const float*)d_in[8];
    const float* bo=(const float*)d_in[9];
    float* out=(float*)d_out;

    f16 *x16,*w16,*qkv16,*q16,*k16,*vt,*o16;
    float *biasqkv,*rsum;
    cudaGetSymbolAddress((void**)&x16,g_x16); cudaGetSymbolAddress((void**)&w16,g_w16);
    cudaGetSymbolAddress((void**)&qkv16,g_qkv16); cudaGetSymbolAddress((void**)&biasqkv,g_biasqkv);
    cudaGetSymbolAddress((void**)&q16,g_q16); cudaGetSymbolAddress((void**)&k16,g_k16);
    cudaGetSymbolAddress((void**)&vt,g_vt);
    cudaGetSymbolAddress((void**)&rsum,g_rsum);
    cudaGetSymbolAddress((void**)&o16,g_o16);

    cudaFuncSetAttribute(gemm_h<0>, cudaFuncAttributeMaxDynamicSharedMemorySize, 65536);
    cudaFuncSetAttribute(gemm_h<1>, cudaFuncAttributeMaxDynamicSharedMemorySize, 65536);
    cudaFuncSetAttribute(colsum_h,  cudaFuncAttributeMaxDynamicSharedMemorySize, 49152);
    cudaFuncSetAttribute(flashpv_h, cudaFuncAttributeMaxDynamicSharedMemorySize, 49152);

    const long NX=(long)ROWS*DM;
    prep<<<dim3((unsigned)((NX/4+255)/256), 5),256>>>(x, Wq, Wk, Wv, Wo, bk, bv, x16, w16, biasqkv);

    gemm_h<1><<<dim3(NQKV/128, ROWS/128),256,65536>>>(x16, w16, biasqkv, nullptr, nullptr, qkv16, DM, NQKV);

    ln2f16<<<dim3(ROWS,2),256>>>(qkv16, gq, gk, q16, k16);

    colsum_h<<<dim3(SEQ/128, ZBN),256,49152>>>(q16, k16, rsum);
    vtscale<<<dim3(SEQ/32, DM/32, 4), dim3(32,8)>>>(qkv16, rsum, vt);
    flashpv_h<<<dim3(SEQ/128, ZBN),256,49152>>>(q16, k16, vt, o16);

    gemm_h<0><<<dim3(DM/128, ROWS/128),256,65536>>>(o16, w16+3*(long)DM*DM, bo, x, out, nullptr, DM, DM);
}

// round 17
// speedup vs baseline: 1.0524x; 1.0524x over previous
#include <cuda_runtime.h>
#include <cuda_fp16.h>
#include <cstdint>

#define SEQ 2048
#define DM 768
#define NH 12
#define HD 64
#define ROWS 8192
#define ZBN 48
#define NQKV 2304
typedef __half f16;

// ---------------- scratch ----------------
__device__ __align__(16) f16  g_x16[ROWS*DM];
__device__ __align__(16) f16  g_w16[4][DM*DM];
__device__ __align__(16) float g_biasqkv[NQKV];
__device__ __align__(16) float g_qkv[(long)ROWS*NQKV];
__device__ __align__(16) f16  g_q16[ROWS*DM], g_k16[ROWS*DM];
__device__ __align__(16) f16  g_vt[(long)ZBN*HD*SEQ];
__device__ __align__(16) float g_rsum[ZBN*SEQ];
__device__ __align__(16) f16  g_o16[ROWS*DM];

#define SWZ(o) ((o)^(((o)>>3)&0x70))
#define CPCOMMIT() asm volatile("cp.async.commit_group;":::"memory")
#define CPWAIT1()  asm volatile("cp.async.wait_group 1;":::"memory")
#define CPWAIT0()  asm volatile("cp.async.wait_group 0;":::"memory")
#define LOG2E 1.44269504f

__device__ __forceinline__ uint32_t smem_u32(const void* p){
    uint32_t a; asm("{ .reg .u64 t; cvta.to.shared.u64 t, %1; cvt.u32.u64 %0, t; }":"=r"(a):"l"(p)); return a;
}
__device__ __forceinline__ float ex2(float x){
    float y; asm("ex2.approx.f32 %0, %1;":"=f"(y):"f"(x)); return y;
}
__device__ __forceinline__ void ldm4(uint32_t* r, uint32_t base, int row0, int ks, int lane){
    uint32_t addr = base + SWZ((unsigned)((row0+(lane&15))<<7) + (unsigned)(((ks<<1)+(lane>>4))<<4));
    asm volatile("ldmatrix.sync.aligned.m8n8.x4.shared.b16 {%0,%1,%2,%3}, [%4];"
        :"=r"(r[0]),"=r"(r[1]),"=r"(r[2]),"=r"(r[3]):"r"(addr));
}
__device__ __forceinline__ void ldm4p(uint32_t* r, uint32_t addr){
    asm volatile("ldmatrix.sync.aligned.m8n8.x4.shared.b16 {%0,%1,%2,%3}, [%4];"
        :"=r"(r[0]),"=r"(r[1]),"=r"(r[2]),"=r"(r[3]):"r"(addr));
}
__device__ __forceinline__ uint32_t ldmaddr(int row0, int ks, int lane){
    return SWZ((unsigned)((row0+(lane&15))<<7) + (unsigned)(((ks<<1)+(lane>>4))<<4));
}
__device__ __forceinline__ void mma_hf(float* d, const uint32_t* a, uint32_t b0, uint32_t b1){
    asm volatile("mma.sync.aligned.m16n8k16.row.col.f32.f16.f16.f32 "
        "{%0,%1,%2,%3},{%4,%5,%6,%7},{%8,%9},{%0,%1,%2,%3};"
        : "+f"(d[0]),"+f"(d[1]),"+f"(d[2]),"+f"(d[3])
        : "r"(a[0]),"r"(a[1]),"r"(a[2]),"r"(a[3]),"r"(b0),"r"(b1));
}
// pack two fp32 scores -> fp16x2, then one f16x2 MUFU exp2. Result = packed P.
__device__ __forceinline__ unsigned packexp2(float a, float b){
    unsigned s,r;
    asm("cvt.rn.f16x2.f32 %0, %1, %2;":"=r"(s):"f"(b),"f"(a));
    asm("ex2.approx.f16x2 %0, %1;":"=r"(r):"r"(s));
    return r;
}
template<int ROWSN, typename T>
__device__ __forceinline__ void cpfill(uint32_t s, const T* __restrict__ g, int ldK, int tid){
#pragma unroll
    for(int i=0;i<ROWSN/32;i++){
        int idx=tid+(i<<8); int r=idx>>3, c=idx&7;
        uint32_t dst=s+SWZ((unsigned)((r<<7)+(c<<4)));
        const void* src=g+(long)r*ldK+(c<<3);
        asm volatile("cp.async.cg.shared.global [%0], [%1], 16;"::"r"(dst),"l"(src):"memory");
    }
}

// ---------------------------------------------------------------------------
// prep: all fp32->fp16 conversions + bias concat in one launch.
// ---------------------------------------------------------------------------
__global__ __launch_bounds__(256) void prep(
    const float* __restrict__ x,
    const float* __restrict__ Wq,const float* __restrict__ Wk,
    const float* __restrict__ Wv,const float* __restrict__ Wo,
    const float* __restrict__ bk,const float* __restrict__ bv,
    f16* __restrict__ x16, f16* __restrict__ w16, float* __restrict__ biasqkv)
{
    const long NX=(long)ROWS*DM, NW=(long)DM*DM;
    int y=blockIdx.y;
    long i=((long)blockIdx.x*256+threadIdx.x)*4;
    const float* src; f16* dst; long n;
    if(y==4){ src=x; dst=x16; n=NX; }
    else { src=(y==0)?Wq:(y==1)?Wk:(y==2)?Wv:Wo; dst=w16+(long)y*NW; n=NW; }
    if(i<n){
        float4 v=*reinterpret_cast<const float4*>(src+i);
        __half2 a=__floats2half2_rn(v.x,v.y), b=__floats2half2_rn(v.z,v.w);
        *reinterpret_cast<uint2*>(dst+i)=make_uint2(*reinterpret_cast<unsigned*>(&a),*reinterpret_cast<unsigned*>(&b));
    }
    if(y==0){
        int j=blockIdx.x*256+threadIdx.x;
        if(j<NQKV) biasqkv[j]=(j<DM)?0.f:((j<2*DM)?bk[j-DM]:bv[j-2*DM]);
    }
}

// ---------------------------------------------------------------------------
// fp16 GEMM, fp32 out: C = A B^T + bias (+resid)
// ---------------------------------------------------------------------------
__global__ __launch_bounds__(256) void gemm_h(
    const f16* __restrict__ a16,const f16* __restrict__ b16,
    const float* __restrict__ bias,const float* __restrict__ resid,
    float* __restrict__ C,int K,int N)
{
    extern __shared__ char smem[];
    const uint32_t sb=smem_u32(smem);
    const int tid=threadIdx.x, wid=tid>>5, lane=tid&31;
    const int m0=blockIdx.y<<7, n0=blockIdx.x<<7;
    const int wm=(wid&3)<<5, wn=(wid>>2)<<6;
    const f16* A=a16+(long)m0*K;
    const f16* B=b16+(long)n0*K;
    const int NS=K>>6;

    cpfill<128>(sb,       A, K, tid);
    cpfill<128>(sb+16384, B, K, tid);
    CPCOMMIT();

    float acc[2][8][4]={};
    for(int s=0;s<NS;s++){
        if(s+1<NS){
            uint32_t st=sb+((s+1)&1)*32768;
            cpfill<128>(st,       A+(s+1)*64, K, tid);
            cpfill<128>(st+16384, B+(s+1)*64, K, tid);
            CPCOMMIT(); CPWAIT1();
        } else CPWAIT0();
        __syncthreads();
        const uint32_t sA=sb+(s&1)*32768, sB=sA+16384;
#pragma unroll
        for(int ks=0;ks<4;ks++){
            uint32_t av[2][4];
            ldm4(av[0], sA, wm,    ks, lane); ldm4(av[1], sA, wm+16, ks, lane);
            uint32_t bv[4][4];
#pragma unroll
            for(int j=0;j<4;j++) ldm4(bv[j], sB, wn+(j<<4), ks, lane);
#pragma unroll
            for(int mi=0;mi<2;mi++)
#pragma unroll
                for(int j=0;j<4;j++){
                    mma_hf(acc[mi][2*j],   av[mi], bv[j][0], bv[j][2]);
                    mma_hf(acc[mi][2*j+1], av[mi], bv[j][1], bv[j][3]);
                }
        }
        __syncthreads();
    }
#pragma unroll
    for(int mi=0;mi<2;mi++)
#pragma unroll
        for(int jj=0;jj<8;jj++){
            float* d=acc[mi][jj];
            int col=n0+wn+(jj<<3)+((lane&3)<<1);
            long row=m0+wm+(mi<<4)+(lane>>2);
            float2 v0=make_float2(d[0],d[1]), v1=make_float2(d[2],d[3]);
            float2 bv=*reinterpret_cast<const float2*>(bias+col);
            v0.x+=bv.x; v0.y+=bv.y; v1.x+=bv.x; v1.y+=bv.y;
            if(resid){
                float2 r0=*reinterpret_cast<const float2*>(resid+row*N+col);
                float2 r1=*reinterpret_cast<const float2*>(resid+(row+8)*N+col);
                v0.x+=r0.x; v0.y+=r0.y; v1.x+=r1.x; v1.y+=r1.y;
            }
            *reinterpret_cast<float2*>(C+row*N+col)=v0;
            *reinterpret_cast<float2*>(C+(row+8)*N+col)=v1;
        }
}

// ---- LN (no bias) on fp32 qkv; y=0 -> q (0.125*log2e folded), y=1 -> k (1.0) ----
__global__ __launch_bounds__(256) void ln2f16(
    const float* __restrict__ qkv, const float* __restrict__ gq, const float* __restrict__ gk,
    f16* __restrict__ q16, f16* __restrict__ k16)
{
    const int y=blockIdx.y;
    const long row=blockIdx.x;
    const float* p=qkv+row*NQKV+(y?DM:0);
    const float* gamma=y?gk:gq;
    const float scale=y?1.0f:(0.125f*LOG2E);   // log2e folded into q ONLY
    f16* out=(y?k16:q16)+row*DM;
    const int t=threadIdx.x;

    float v0=p[t],v1=p[t+256],v2=p[t+512];
    float s=v0+v1+v2, sq=v0*v0+v1*v1+v2*v2;
#pragma unroll
    for(int o=16;o;o>>=1){ s+=__shfl_xor_sync(~0u,s,o); sq+=__shfl_xor_sync(~0u,sq,o); }
    __shared__ float ss[8],sqs[8];
    int w=t>>5,ln=t&31;
    if(ln==0){ss[w]=s;sqs[w]=sq;} __syncthreads();
    if(w==0){ s=(ln<8)?ss[ln]:0.f; sq=(ln<8)?sqs[ln]:0.f;
#pragma unroll
        for(int o=4;o;o>>=1){ s+=__shfl_xor_sync(~0u,s,o); sq+=__shfl_xor_sync(~0u,sq,o); }
        if(ln==0){ss[0]=s;sqs[0]=sq;} }
    __syncthreads();
    float mu=ss[0]*(1.f/DM), var=sqs[0]*(1.f/DM)-mu*mu, rstd=rsqrtf(var+1e-5f)*scale;
#pragma unroll
    for(int g=0;g<3;g++){
        int c=t+g*256; float yv=((g==0?v0:g==1?v1:v2)-mu)*rstd*gamma[c];
        out[c]=__float2half_rn(yv);
    }
}

// ---------------------------------------------------------------------------
// Pass 1: rsum[z][k] = 1/sum_q 2^S (log2e pre-folded into q). K-tile resident.
// (R15/R16 version — measured 95.2us)
// ---------------------------------------------------------------------------
__global__ __launch_bounds__(256) void colsum_h(
    const f16* __restrict__ q16,const f16* __restrict__ k16, float* __restrict__ rsum)
{
    extern __shared__ char smem[];
    const uint32_t sb=smem_u32(smem);
    const int tid=threadIdx.x, wid=tid>>5, lane=tid&31;
    const int z=blockIdx.y, b=z/NH, h=z-b*NH;
    const int k0=blockIdx.x<<7;
    const int wm=(wid&3)<<5, wng=wid>>2;
    const f16* Kp=k16+(long)(b*SEQ+k0)*DM+h*HD;
    const f16* Qp=q16+(long)(b*SEQ)*DM+h*HD;

    cpfill<128>(sb, Kp, DM, tid);
    cpfill<128>(sb+16384, Qp, DM, tid);
    CPCOMMIT(); CPWAIT0();
    __syncthreads();

    uint32_t ka[2][4][4];
#pragma unroll
    for(int mi=0;mi<2;mi++)
#pragma unroll
        for(int ks=0;ks<4;ks++) ldm4(ka[mi][ks], sb, wm+(mi<<4), ks, lane);

    uint32_t qrel[4][4];
#pragma unroll
    for(int ks=0;ks<4;ks++)
#pragma unroll
        for(int j=0;j<4;j++) qrel[ks][j]=ldmaddr((wng<<6)+(j<<4), ks, lane)+sb+16384;

    float rs[2][2]={};
    for(int s=0;s<16;s++){
        if(s+1<16){
            cpfill<128>(sb+16384+((s+1)&1)*16384, Qp+(long)(s+1)*128*DM, DM, tid);
            CPCOMMIT(); CPWAIT1();
        } else CPWAIT0();
        __syncthreads();
        const uint32_t soff=(s&1)*16384;
        float acc[2][8][4]={};
#pragma unroll
        for(int ks=0;ks<4;ks++){
            uint32_t bv[4][4];
#pragma unroll
            for(int j=0;j<4;j++) ldm4p(bv[j], qrel[ks][j]+soff);
#pragma unroll
            for(int mi=0;mi<2;mi++)
#pragma unroll
                for(int j=0;j<4;j++){
                    mma_hf(acc[mi][2*j],   ka[mi][ks], bv[j][0], bv[j][2]);
                    mma_hf(acc[mi][2*j+1], ka[mi][ks], bv[j][1], bv[j][3]);
                }
        }
#pragma unroll
        for(int mi=0;mi<2;mi++)
#pragma unroll
            for(int jj=0;jj<8;jj++){
                float* d=acc[mi][jj];
                rs[mi][0]+=ex2(d[0])+ex2(d[1]);
                rs[mi][1]+=ex2(d[2])+ex2(d[3]);
            }
        __syncthreads();
    }
    __shared__ float cs[2][128];
#pragma unroll
    for(int mi=0;mi<2;mi++)
#pragma unroll
        for(int p=0;p<2;p++){
            float v=rs[mi][p];
            v+=__shfl_xor_sync(~0u,v,1); v+=__shfl_xor_sync(~0u,v,2);
            if((lane&3)==0) cs[wng][wm+(mi<<4)+(p<<3)+(lane>>2)]=v;
        }
    __syncthreads();
    if(tid<128){
        float s=cs[0][tid]+cs[1][tid];
        rsum[(long)z*SEQ+k0+tid]=1.f/s;
    }
}

// ---- qkv v-part (fp32) -> vt fp16 [z][64][2048], scaled by rsum ----
__global__ void vtscale(const float* __restrict__ qkv, const float* __restrict__ rsum,
                        f16* __restrict__ vt){
    __shared__ float tile[32][33];
    int b=blockIdx.z, c0=blockIdx.y*32, t0=blockIdx.x*32;
    int tx=threadIdx.x, ty=threadIdx.y;
#pragma unroll
    for(int j=0;j<32;j+=8)
        tile[ty+j][tx]=qkv[(long)(b*SEQ+t0+ty+j)*NQKV+2*DM+c0+tx];
    __syncthreads();
    int z=b*NH+(c0>>6), ch=c0&63;
    float rs=rsum[z*SEQ+t0+tx];
#pragma unroll
    for(int j=0;j<32;j+=8){
        long o=((long)z*HD+ch+ty+j)*SEQ+t0+tx;
        vt[o]=__float2half_rn(tile[tx][ty+j]*rs);
    }
}

// ---------------------------------------------------------------------------
// Pass 2: fused scores+PV (flash-style). Inline ldmatrix addressing; P via
// cvt+ex2.f16x2 (one MUFU per 2 values). E never hits DRAM.
// ---------------------------------------------------------------------------
__global__ __launch_bounds__(256) void flashpv_h(
    const f16* __restrict__ q16,const f16* __restrict__ k16,
    const f16* __restrict__ vt, f16* __restrict__ o16)
{
    extern __shared__ char smem[];
    const uint32_t sb=smem_u32(smem);
    const int tid=threadIdx.x, wid=tid>>5, lane=tid&31;
    const int z=blockIdx.y, b=z/NH, h=z-b*NH;
    const int q0=blockIdx.x<<7;
    const int wq=wid<<4;
    const f16* Qp=q16+(long)(b*SEQ+q0)*DM+h*HD;
    const f16* Kp=k16+(long)(b*SEQ)*DM+h*HD;
    const f16* Vp=vt+(long)z*HD*SEQ;

    cpfill<128>(sb, Qp, DM, tid);
    {
        uint32_t st=sb+16384;
        cpfill<64>(st,      Kp, DM, tid);
        cpfill<64>(st+8192, Vp, SEQ, tid);
    }
    CPCOMMIT(); CPWAIT0();
    __syncthreads();

    uint32_t qa[4][4];
#pragma unroll
    for(int ks=0;ks<4;ks++) ldm4(qa[ks], sb, wq, ks, lane);

    float accp[8][4]={};
    for(int s=0;s<32;s++){
        if(s+1<32){
            uint32_t st=sb+16384+((s+1)&1)*16384;
            cpfill<64>(st,      Kp+(long)(s+1)*64*DM, DM, tid);
            cpfill<64>(st+8192, Vp+(s+1)*64, SEQ, tid);
            CPCOMMIT(); CPWAIT1();
        } else CPWAIT0();
        __syncthreads();
        const uint32_t sK=sb+16384+(s&1)*16384, sV=sK+8192;

        float accs[8][4]={};
#pragma unroll
        for(int ks=0;ks<4;ks++){
            uint32_t bv[4][4];
#pragma unroll
            for(int j=0;j<4;j++) ldm4(bv[j], sK, j<<4, ks, lane);
#pragma unroll
            for(int j=0;j<4;j++){
                mma_hf(accs[2*j],   qa[ks], bv[j][0], bv[j][2]);
                mma_hf(accs[2*j+1], qa[ks], bv[j][1], bv[j][3]);
            }
        }
        uint32_t pa[4][4];
#pragma unroll
        for(int g=0;g<4;g++){
            float* cl=accs[2*g]; float* ch=accs[2*g+1];
            pa[g][0]=packexp2(cl[0],cl[1]);
            pa[g][1]=packexp2(cl[2],cl[3]);
            pa[g][2]=packexp2(ch[0],ch[1]);
            pa[g][3]=packexp2(ch[2],ch[3]);
        }
#pragma unroll
        for(int g=0;g<4;g++){
            uint32_t bv[4][4];
#pragma unroll
            for(int j=0;j<4;j++) ldm4(bv[j], sV, j<<4, g, lane);
#pragma unroll
            for(int j=0;j<4;j++){
                mma_hf(accp[2*j],   pa[g], bv[j][0], bv[j][2]);
                mma_hf(accp[2*j+1], pa[g], bv[j][1], bv[j][3]);
            }
        }
        __syncthreads();
    }
#pragma unroll
    for(int jj=0;jj<8;jj++){
        float* d=accp[jj];
        int col=h*HD+(jj<<3)+((lane&3)<<1);
        long row=(long)b*SEQ+q0+wq+(lane>>2);
        __half2 p0=__floats2half2_rn(d[0],d[1]), p1=__floats2half2_rn(d[2],d[3]);
        *reinterpret_cast<unsigned*>(o16+row*DM+col)=*reinterpret_cast<unsigned*>(&p0);
        *reinterpret_cast<unsigned*>(o16+(row+8)*DM+col)=*reinterpret_cast<unsigned*>(&p1);
    }
}

extern "C" void kernel_launch(void* const* d_in, const int* in_sizes, int n_in,
                              void* d_out, int out_size)
{
    const float* x =(const float*)d_in[0];
    const float* Wq=(const float*)d_in[1];
    const float* Wk=(const float*)d_in[2];
    const float* bk=(const float*)d_in[3];
    const float* Wv=(const float*)d_in[4];
    const float* bv=(const float*)d_in[5];
    const float* gq=(const float*)d_in[6];
    const float* gk=(const float*)d_in[7];
    const float* Wo=(const float*)d_in[8];
    const float* bo=(const float*)d_in[9];
    float* out=(float*)d_out;

    f16 *x16,*w16,*q16,*k16,*vt,*o16;
    float *qkv,*biasqkv,*rsum;
    cudaGetSymbolAddress((void**)&x16,g_x16); cudaGetSymbolAddress((void**)&w16,g_w16);
    cudaGetSymbolAddress((void**)&qkv,g_qkv); cudaGetSymbolAddress((void**)&biasqkv,g_biasqkv);
    cudaGetSymbolAddress((void**)&q16,g_q16); cudaGetSymbolAddress((void**)&k16,g_k16);
    cudaGetSymbolAddress((void**)&vt,g_vt);
    cudaGetSymbolAddress((void**)&rsum,g_rsum);
    cudaGetSymbolAddress((void**)&o16,g_o16);

    cudaFuncSetAttribute(gemm_h,    cudaFuncAttributeMaxDynamicSharedMemorySize, 65536);
    cudaFuncSetAttribute(colsum_h,  cudaFuncAttributeMaxDynamicSharedMemorySize, 49152);
    cudaFuncSetAttribute(flashpv_h, cudaFuncAttributeMaxDynamicSharedMemorySize, 49152);

    const long NX=(long)ROWS*DM;
    prep<<<dim3((unsigned)((NX/4+255)/256), 5),256>>>(x, Wq, Wk, Wv, Wo, bk, bv, x16, w16, biasqkv);

    // fused QKV projection -> fp32 (R13 dataflow)
    gemm_h<<<dim3(NQKV/128, ROWS/128),256,65536>>>(x16, w16, biasqkv, nullptr, qkv, DM, NQKV);

    ln2f16<<<dim3(ROWS,2),256>>>(qkv, gq, gk, q16, k16);

    colsum_h<<<dim3(SEQ/128, ZBN),256,49152>>>(q16, k16, rsum);
    vtscale<<<dim3(SEQ/32, DM/32, 4), dim3(32,8)>>>(qkv, rsum, vt);
    flashpv_h<<<dim3(SEQ/128, ZBN),256,49152>>>(q16, k16, vt, o16);

    gemm_h<<<dim3(DM/128, ROWS/128),256,65536>>>(o16, w16+3*(long)DM*DM, bo, x, out, DM, DM);
}